// round 10
// baseline (speedup 1.0000x reference)
#include <cuda_runtime.h>
#include <cuda_fp16.h>
#include <mma.h>
#include <cstdint>
#include <type_traits>

using namespace nvcuda;

// FHEAttention B=4,S=4096,E=256 — linearized: out = 1e-11 * x @ P @ (x^T x) @ R
// All GEMMs on HMMA (wmma fp16, fp32 accumulate). 1e-11 applied in final epilogue.
// Split-K reduce folded into U2 GEMM (K=2048 over fp32 partials, converted in
// staging); weight fp32->fp16 conversion folded into chain staging.

#define B_ 4
#define S_ 4096
#define E_ 256
#define GSPLIT 8
#define PAD32 40
#define PADM 136

// ---------------- scratch ----------------
__device__ __align__(128) __half g_xTh[B_ * E_ * S_];    // x^T fp16
__device__ __align__(128) float  g_part[B_ * GSPLIT * E_ * E_];
__device__ __align__(128) __half g_R2h[E_ * E_];
__device__ __align__(128) __half g_P2h[E_ * E_];
__device__ __align__(128) __half g_U2h[B_ * E_ * E_];
__device__ __align__(128) __half g_T2h[B_ * E_ * E_];

// ---------------- generic fp16 wmma GEMM body, 128x128 CTA tile --------------
// C[m,n] = alpha * sum_k A(m,k) * B(k,n); pointers pre-offset by caller.
// AT=0: A stored [m][k];  AT=1: A stored [k][m].  BT likewise for B.
// TA/TB = __half or float (float sources converted to fp16 during staging).
// OUTH=0: C fp32; OUTH=1: C fp16.
// kmaskA: A's k index is (kt & kmaskA)  (used to cycle R2 in the fused reduce).
template <int AT, int BT, int OUTH, typename TA, typename TB>
__device__ __forceinline__ void gemm_body(
    const TA* Ap, const TB* Bp, void* Cv,
    int lda, int ldb, int ldc, int Kc, int kmaskA, float alpha,
    __half* As, __half* Bs)
{
    constexpr bool A32 = std::is_same<TA, float>::value;
    constexpr bool B32 = std::is_same<TB, float>::value;
    const int tid = threadIdx.x, wid = tid >> 5;
    const int warp_m = (wid & 1) * 64;   // 2 warps over m
    const int warp_n = (wid >> 1) * 32;  // 4 warps over n

    wmma::fragment<wmma::accumulator, 16, 16, 16, float> acc[4][2];
    #pragma unroll
    for (int i = 0; i < 4; i++)
        #pragma unroll
        for (int j = 0; j < 2; j++)
            wmma::fill_fragment(acc[i][j], 0.0f);

    using ALay = std::conditional_t<AT == 0, wmma::row_major, wmma::col_major>;
    using BLay = std::conditional_t<BT == 0, wmma::row_major, wmma::col_major>;

    for (int kt = 0; kt < Kc; kt += 32) {
        // ---- stage A ----
        if constexpr (AT == 0) {
            if constexpr (!A32) {
                const __half* Aq = (const __half*)Ap + (kt & kmaskA);
                #pragma unroll
                for (int q = 0; q < 2; q++) {
                    int idx = tid + q * 256;
                    int r = idx >> 2, c = (idx & 3) * 8;
                    *(uint4*)(As + r * PAD32 + c) = *(const uint4*)(Aq + (long)r * lda + c);
                }
            } else {
                const float* Aq = (const float*)Ap + (kt & kmaskA);
                #pragma unroll
                for (int q = 0; q < 4; q++) {
                    int idx = tid + q * 256;
                    int r = idx >> 3, c = (idx & 7) * 4;
                    float4 v = *(const float4*)(Aq + (long)r * lda + c);
                    __half2 h0 = __floats2half2_rn(v.x, v.y);
                    __half2 h1 = __floats2half2_rn(v.z, v.w);
                    uint2 o; o.x = *(uint32_t*)&h0; o.y = *(uint32_t*)&h1;
                    *(uint2*)(As + r * PAD32 + c) = o;
                }
            }
        } else {
            if constexpr (!A32) {
                const __half* Aq = (const __half*)Ap + (long)kt * lda;
                #pragma unroll
                for (int q = 0; q < 2; q++) {
                    int idx = tid + q * 256;
                    int r = idx >> 4, c = (idx & 15) * 8;
                    *(uint4*)(As + r * PADM + c) = *(const uint4*)(Aq + (long)r * lda + c);
                }
            } else {
                const float* Aq = (const float*)Ap + (long)kt * lda;
                #pragma unroll
                for (int q = 0; q < 4; q++) {
                    int idx = tid + q * 256;
                    int r = idx >> 5, c = (idx & 31) * 4;
                    float4 v = *(const float4*)(Aq + (long)r * lda + c);
                    __half2 h0 = __floats2half2_rn(v.x, v.y);
                    __half2 h1 = __floats2half2_rn(v.z, v.w);
                    uint2 o; o.x = *(uint32_t*)&h0; o.y = *(uint32_t*)&h1;
                    *(uint2*)(As + r * PADM + c) = o;
                }
            }
        }
        // ---- stage B ----
        if constexpr (BT == 0) {
            if constexpr (!B32) {
                const __half* Bq = (const __half*)Bp + (long)kt * ldb;
                #pragma unroll
                for (int q = 0; q < 2; q++) {
                    int idx = tid + q * 256;
                    int r = idx >> 4, c = (idx & 15) * 8;
                    *(uint4*)(Bs + r * PADM + c) = *(const uint4*)(Bq + (long)r * ldb + c);
                }
            } else {
                const float* Bq = (const float*)Bp + (long)kt * ldb;
                #pragma unroll
                for (int q = 0; q < 4; q++) {
                    int idx = tid + q * 256;
                    int r = idx >> 5, c = (idx & 31) * 4;
                    float4 v = *(const float4*)(Bq + (long)r * ldb + c);
                    __half2 h0 = __floats2half2_rn(v.x, v.y);
                    __half2 h1 = __floats2half2_rn(v.z, v.w);
                    uint2 o; o.x = *(uint32_t*)&h0; o.y = *(uint32_t*)&h1;
                    *(uint2*)(Bs + r * PADM + c) = o;
                }
            }
        } else {
            if constexpr (!B32) {
                const __half* Bq = (const __half*)Bp + kt;
                #pragma unroll
                for (int q = 0; q < 2; q++) {
                    int idx = tid + q * 256;
                    int r = idx >> 2, c = (idx & 3) * 8;
                    *(uint4*)(Bs + r * PAD32 + c) = *(const uint4*)(Bq + (long)r * ldb + c);
                }
            } else {
                const float* Bq = (const float*)Bp + kt;
                #pragma unroll
                for (int q = 0; q < 4; q++) {
                    int idx = tid + q * 256;
                    int r = idx >> 3, c = (idx & 7) * 4;
                    float4 v = *(const float4*)(Bq + (long)r * ldb + c);
                    __half2 h0 = __floats2half2_rn(v.x, v.y);
                    __half2 h1 = __floats2half2_rn(v.z, v.w);
                    uint2 o; o.x = *(uint32_t*)&h0; o.y = *(uint32_t*)&h1;
                    *(uint2*)(Bs + r * PAD32 + c) = o;
                }
            }
        }
        __syncthreads();
        #pragma unroll
        for (int ks = 0; ks < 32; ks += 16) {
            wmma::fragment<wmma::matrix_a, 16, 16, 16, __half, ALay> af[4];
            wmma::fragment<wmma::matrix_b, 16, 16, 16, __half, BLay> bf[2];
            #pragma unroll
            for (int i = 0; i < 4; i++) {
                if constexpr (AT == 0)
                    wmma::load_matrix_sync(af[i], As + (warp_m + i * 16) * PAD32 + ks, PAD32);
                else
                    wmma::load_matrix_sync(af[i], As + ks * PADM + warp_m + i * 16, PADM);
            }
            #pragma unroll
            for (int j = 0; j < 2; j++) {
                if constexpr (BT == 0)
                    wmma::load_matrix_sync(bf[j], Bs + ks * PADM + warp_n + j * 16, PADM);
                else
                    wmma::load_matrix_sync(bf[j], Bs + (warp_n + j * 16) * PAD32 + ks, PAD32);
            }
            #pragma unroll
            for (int i = 0; i < 4; i++)
                #pragma unroll
                for (int j = 0; j < 2; j++)
                    wmma::mma_sync(acc[i][j], af[i], bf[j], acc[i][j]);
        }
        __syncthreads();
    }

    if constexpr (OUTH == 0) {
        float* Cb = (float*)Cv;
        #pragma unroll
        for (int i = 0; i < 4; i++)
            #pragma unroll
            for (int j = 0; j < 2; j++) {
                #pragma unroll
                for (int t = 0; t < acc[i][j].num_elements; t++)
                    acc[i][j].x[t] *= alpha;
                wmma::store_matrix_sync(Cb + (long)(warp_m + i * 16) * ldc + warp_n + j * 16,
                                        acc[i][j], ldc, wmma::mem_row_major);
            }
    } else {
        __half* Cb = (__half*)Cv;
        float* patch = ((float*)As) + wid * 256;   // 1KB/warp inside As (8KB total)
        const int lane = tid & 31;
        #pragma unroll
        for (int i = 0; i < 4; i++)
            #pragma unroll
            for (int j = 0; j < 2; j++) {
                wmma::store_matrix_sync(patch, acc[i][j], 16, wmma::mem_row_major);
                __syncwarp();
                #pragma unroll
                for (int e = 0; e < 8; e++) {
                    int el = lane + e * 32;
                    int rr = el >> 4, cc = el & 15;
                    Cb[(long)(warp_m + i * 16 + rr) * ldc + warp_n + j * 16 + cc] =
                        __float2half(patch[el] * alpha);
                }
                __syncwarp();
            }
    }
}

// ---------------- generic fp16 kernel wrapper ----------------
// blockIdx.x = m_block*2 + n_block; blockIdx.y = k-split chunk; blockIdx.z = batch.
template <int AT, int BT, int OUTH>
__global__ __launch_bounds__(256, 2) void gemm_k(
    const __half* __restrict__ A, const __half* __restrict__ B, void* Cv,
    int lda, int ldb, int ldc, int Kc,
    long sAz, long sBz, long sCz, long sCy, float alpha)
{
    __shared__ __align__(32) __half As[128 * PAD32];
    __shared__ __align__(32) __half Bs[128 * PAD32];
    const int bx = blockIdx.x, by = blockIdx.y, bz = blockIdx.z;
    const int m0 = (bx >> 1) * 128, n0 = (bx & 1) * 128;

    const __half* Ab;
    if constexpr (AT == 0) Ab = A + (long)bz * sAz + (long)m0 * lda + (long)by * Kc;
    else                   Ab = A + (long)bz * sAz + (long)by * Kc * lda + m0;
    const __half* Bb;
    if constexpr (BT == 0) Bb = B + (long)bz * sBz + (long)by * Kc * ldb + n0;
    else                   Bb = B + (long)bz * sBz + (long)n0 * ldb + (long)by * Kc;
    const long coff = (long)bz * sCz + (long)by * sCy + (long)m0 * ldc + n0;
    void* Cb;
    if constexpr (OUTH == 0) Cb = (void*)((float*)Cv + coff);
    else                     Cb = (void*)((__half*)Cv + coff);

    gemm_body<AT, BT, OUTH>(Ab, Bb, Cb, lda, ldb, ldc, Kc, ~0, alpha, As, Bs);
}

// ---------------- merged weight-product kernel (fp32 sources) ---------------
// z=0: R2[g,e] = sum_f Wo[g,f] Wv[f,e]   (AT=0, BT=0)
// z=1: P2[a,e] = sum_f Wk[f,a] Wq[f,e]   (AT=1, BT=0)
__global__ __launch_bounds__(256, 2) void chain_wp2(
    const float* __restrict__ Wo, const float* __restrict__ Wv,
    const float* __restrict__ Wk, const float* __restrict__ Wq,
    __half* __restrict__ R2, __half* __restrict__ P2)
{
    __shared__ __align__(32) __half As[128 * PAD32];
    __shared__ __align__(32) __half Bs[128 * PAD32];
    const int bx = blockIdx.x;
    const int m0 = (bx >> 1) * 128, n0 = (bx & 1) * 128;
    if (blockIdx.z == 0) {
        gemm_body<0, 0, 1>(Wo + (long)m0 * E_, Wv + n0,
                           (void*)(R2 + (long)m0 * E_ + n0),
                           E_, E_, E_, E_, ~0, 1.0f, As, Bs);
    } else {
        gemm_body<1, 0, 1>(Wk + m0, Wq + n0,
                           (void*)(P2 + (long)m0 * E_ + n0),
                           E_, E_, E_, E_, ~0, 1.0f, As, Bs);
    }
}

// ---------------- fused reduce + U2: U2_b = R2 · (sum_p part_b,p) ------------
// Extended K = GSPLIT*256 over stacked fp32 partials [2048][256];
// A (R2, fp16) k-index cycles mod 256 via kmaskA = 255.
__global__ __launch_bounds__(256, 2) void u2red(
    const __half* __restrict__ R2, const float* __restrict__ part,
    __half* __restrict__ U2)
{
    __shared__ __align__(32) __half As[128 * PAD32];
    __shared__ __align__(32) __half Bs[128 * PAD32];
    const int bx = blockIdx.x, bz = blockIdx.z;
    const int m0 = (bx >> 1) * 128, n0 = (bx & 1) * 128;
    const long EE = (long)E_ * E_;
    gemm_body<0, 0, 1>(
        R2 + (long)m0 * E_,
        part + (long)bz * GSPLIT * EE + n0,
        (void*)(U2 + (long)bz * EE + (long)m0 * E_ + n0),
        E_, E_, E_, GSPLIT * E_, 255, 1.0f, As, Bs);
}

// ---------------- convert x -> fp16 transposed [b][e][s] ----------
__global__ __launch_bounds__(256) void convert_x(
    const float* __restrict__ x, __half* __restrict__ xTh)
{
    __shared__ __half sh[32][33];
    const int e0 = blockIdx.x * 32, s0 = blockIdx.y * 32, b = blockIdx.z;
    const int j = threadIdx.x & 31, i0 = (threadIdx.x >> 5) * 4;
    const long xb = (long)b * S_ * E_;
    #pragma unroll
    for (int ii = 0; ii < 4; ii++) {
        int i = i0 + ii;
        sh[i][j] = __float2half(x[xb + (long)(s0 + i) * E_ + e0 + j]);
    }
    __syncthreads();
    const long xtb = (long)b * E_ * S_;
    #pragma unroll
    for (int ii = 0; ii < 4; ii++) {
        int i = i0 + ii;
        xTh[xtb + (long)(e0 + i) * S_ + s0 + j] = sh[j][i];
    }
}

// ---------------- launch ----------------
extern "C" void kernel_launch(void* const* d_in, const int* in_sizes, int n_in,
                              void* d_out, int out_size)
{
    const float* x  = (const float*)d_in[0];
    const float* Wq = (const float*)d_in[1];
    const float* Wk = (const float*)d_in[2];
    const float* Wv = (const float*)d_in[3];
    const float* Wo = (const float*)d_in[4];
    float* out = (float*)d_out;

    __half *pxTh, *pR2h, *pP2h, *pU2h, *pT2h;
    float *pPart;
    cudaGetSymbolAddress((void**)&pxTh, g_xTh);
    cudaGetSymbolAddress((void**)&pPart, g_part);
    cudaGetSymbolAddress((void**)&pR2h, g_R2h);
    cudaGetSymbolAddress((void**)&pP2h, g_P2h);
    cudaGetSymbolAddress((void**)&pU2h, g_U2h);
    cudaGetSymbolAddress((void**)&pT2h, g_T2h);

    const long EE = (long)E_ * E_;
    const long ES = (long)E_ * S_;

    // 1) convert x -> fp16 transposed
    convert_x<<<dim3(E_ / 32, S_ / 32, B_), 256>>>(x, pxTh);

    // 2) Gram partials: part[b][p][e][f] = sum over S-chunk of xT[e,s] xT[f,s]
    gemm_k<0, 1, 0><<<dim3(4, GSPLIT, B_), 256>>>(
        pxTh, pxTh, pPart, S_, S_, E_, S_ / GSPLIT,
        ES, ES, (long)GSPLIT * EE, EE, 1.0f);

    // 3) weight chain head: R2 + P2 in one launch (fp32 staged)
    chain_wp2<<<dim3(4, 1, 2), 256>>>(Wo, Wv, Wk, Wq, pR2h, pP2h);

    // 4) fused reduce+U2: U2_b = R2 · (sum_p part_b,p), K = 2048
    u2red<<<dim3(4, 1, B_), 256>>>(pR2h, pPart, pU2h);

    // 5) T2_b = U2_b · P2  (= T^T, unscaled ~1e-2)
    gemm_k<0, 0, 1><<<dim3(4, 1, B_), 256>>>(
        pU2h, pP2h, pT2h, E_, E_, E_, E_, EE, 0, EE, 0, 1.0f);

    // 6) final: out[s,g] = 1e-11 * sum_f xT[f,s] * T2[g,f]  (AT=1, BT=1)
    gemm_k<1, 1, 0><<<dim3((S_ / 128) * 2, 1, B_), 256>>>(
        pxTh, pT2h, out, S_, E_, E_, E_,
        ES, EE, (long)S_ * E_, 0, 1e-11f);
}

// round 11
// speedup vs baseline: 1.7059x; 1.7059x over previous
#include <cuda_runtime.h>
#include <cuda_fp16.h>
#include <mma.h>
#include <cstdint>
#include <type_traits>

using namespace nvcuda;

// FHEAttention B=4,S=4096,E=256 — linearized: out = 1e-11 * x @ P @ (x^T x) @ R
// All GEMMs on HMMA (wmma fp16, fp32 accumulate). 1e-11 applied in final epilogue.
// Middle section (reduce + R2/P2 + U2 + T2) runs as ONE persistent 64-CTA kernel
// with a software grid barrier (all CTAs resident: 64 << 148 SMs).

#define B_ 4
#define S_ 4096
#define E_ 256
#define GSPLIT 8
#define PAD32 40
#define PADM 136

// ---------------- scratch ----------------
__device__ __align__(128) __half g_xTh[B_ * E_ * S_];    // x^T fp16
__device__ __align__(128) float  g_part[B_ * GSPLIT * E_ * E_];
__device__ __align__(128) __half g_Gh[B_ * E_ * E_];
__device__ __align__(128) __half g_R2h[E_ * E_];
__device__ __align__(128) __half g_P2h[E_ * E_];
__device__ __align__(128) __half g_U2h[B_ * E_ * E_];
__device__ __align__(128) __half g_T2h[B_ * E_ * E_];
__device__ unsigned g_bar_arr = 0;
__device__ unsigned g_bar_gen = 0;

// ---------------- software grid barrier (all CTAs resident) ----------------
__device__ __forceinline__ void grid_barrier(unsigned nCTA) {
    __syncthreads();
    if (threadIdx.x == 0) {
        unsigned gen = atomicAdd(&g_bar_gen, 0u);
        __threadfence();
        unsigned t = atomicAdd(&g_bar_arr, 1u);
        if (t == nCTA - 1) {
            atomicExch(&g_bar_arr, 0u);
            __threadfence();
            atomicAdd(&g_bar_gen, 1u);
        } else {
            while (atomicAdd(&g_bar_gen, 0u) == gen) { }
        }
    }
    __syncthreads();
}

// ---------------- generic fp16 wmma GEMM body, 128x128 CTA tile --------------
// C[m,n] = alpha * sum_k A(m,k) * B(k,n); pointers pre-offset by caller.
// AT=0: A stored [m][k];  AT=1: A stored [k][m].  BT likewise for B.
// TA/TB = __half or float (float sources converted to fp16 during staging).
// OUTH=0: C fp32; OUTH=1: C fp16.
template <int AT, int BT, int OUTH, typename TA, typename TB>
__device__ __forceinline__ void gemm_body(
    const TA* Ap, const TB* Bp, void* Cv,
    int lda, int ldb, int ldc, int Kc, float alpha,
    __half* As, __half* Bs)
{
    constexpr bool A32 = std::is_same<TA, float>::value;
    constexpr bool B32 = std::is_same<TB, float>::value;
    const int tid = threadIdx.x, wid = tid >> 5;
    const int warp_m = (wid & 1) * 64;   // 2 warps over m
    const int warp_n = (wid >> 1) * 32;  // 4 warps over n

    wmma::fragment<wmma::accumulator, 16, 16, 16, float> acc[4][2];
    #pragma unroll
    for (int i = 0; i < 4; i++)
        #pragma unroll
        for (int j = 0; j < 2; j++)
            wmma::fill_fragment(acc[i][j], 0.0f);

    using ALay = std::conditional_t<AT == 0, wmma::row_major, wmma::col_major>;
    using BLay = std::conditional_t<BT == 0, wmma::row_major, wmma::col_major>;

    for (int kt = 0; kt < Kc; kt += 32) {
        // ---- stage A ----
        if constexpr (AT == 0) {
            if constexpr (!A32) {
                const __half* Aq = (const __half*)Ap + kt;
                #pragma unroll
                for (int q = 0; q < 2; q++) {
                    int idx = tid + q * 256;
                    int r = idx >> 2, c = (idx & 3) * 8;
                    *(uint4*)(As + r * PAD32 + c) = *(const uint4*)(Aq + (long)r * lda + c);
                }
            } else {
                const float* Aq = (const float*)Ap + kt;
                #pragma unroll
                for (int q = 0; q < 4; q++) {
                    int idx = tid + q * 256;
                    int r = idx >> 3, c = (idx & 7) * 4;
                    float4 v = *(const float4*)(Aq + (long)r * lda + c);
                    __half2 h0 = __floats2half2_rn(v.x, v.y);
                    __half2 h1 = __floats2half2_rn(v.z, v.w);
                    uint2 o; o.x = *(uint32_t*)&h0; o.y = *(uint32_t*)&h1;
                    *(uint2*)(As + r * PAD32 + c) = o;
                }
            }
        } else {
            if constexpr (!A32) {
                const __half* Aq = (const __half*)Ap + (long)kt * lda;
                #pragma unroll
                for (int q = 0; q < 2; q++) {
                    int idx = tid + q * 256;
                    int r = idx >> 4, c = (idx & 15) * 8;
                    *(uint4*)(As + r * PADM + c) = *(const uint4*)(Aq + (long)r * lda + c);
                }
            } else {
                const float* Aq = (const float*)Ap + (long)kt * lda;
                #pragma unroll
                for (int q = 0; q < 4; q++) {
                    int idx = tid + q * 256;
                    int r = idx >> 5, c = (idx & 31) * 4;
                    float4 v = *(const float4*)(Aq + (long)r * lda + c);
                    __half2 h0 = __floats2half2_rn(v.x, v.y);
                    __half2 h1 = __floats2half2_rn(v.z, v.w);
                    uint2 o; o.x = *(uint32_t*)&h0; o.y = *(uint32_t*)&h1;
                    *(uint2*)(As + r * PADM + c) = o;
                }
            }
        }
        // ---- stage B ----
        if constexpr (BT == 0) {
            if constexpr (!B32) {
                const __half* Bq = (const __half*)Bp + (long)kt * ldb;
                #pragma unroll
                for (int q = 0; q < 2; q++) {
                    int idx = tid + q * 256;
                    int r = idx >> 4, c = (idx & 15) * 8;
                    *(uint4*)(Bs + r * PADM + c) = *(const uint4*)(Bq + (long)r * ldb + c);
                }
            } else {
                const float* Bq = (const float*)Bp + (long)kt * ldb;
                #pragma unroll
                for (int q = 0; q < 4; q++) {
                    int idx = tid + q * 256;
                    int r = idx >> 5, c = (idx & 31) * 4;
                    float4 v = *(const float4*)(Bq + (long)r * ldb + c);
                    __half2 h0 = __floats2half2_rn(v.x, v.y);
                    __half2 h1 = __floats2half2_rn(v.z, v.w);
                    uint2 o; o.x = *(uint32_t*)&h0; o.y = *(uint32_t*)&h1;
                    *(uint2*)(Bs + r * PADM + c) = o;
                }
            }
        } else {
            if constexpr (!B32) {
                const __half* Bq = (const __half*)Bp + kt;
                #pragma unroll
                for (int q = 0; q < 2; q++) {
                    int idx = tid + q * 256;
                    int r = idx >> 2, c = (idx & 3) * 8;
                    *(uint4*)(Bs + r * PAD32 + c) = *(const uint4*)(Bq + (long)r * ldb + c);
                }
            } else {
                const float* Bq = (const float*)Bp + kt;
                #pragma unroll
                for (int q = 0; q < 4; q++) {
                    int idx = tid + q * 256;
                    int r = idx >> 3, c = (idx & 7) * 4;
                    float4 v = *(const float4*)(Bq + (long)r * ldb + c);
                    __half2 h0 = __floats2half2_rn(v.x, v.y);
                    __half2 h1 = __floats2half2_rn(v.z, v.w);
                    uint2 o; o.x = *(uint32_t*)&h0; o.y = *(uint32_t*)&h1;
                    *(uint2*)(Bs + r * PAD32 + c) = o;
                }
            }
        }
        __syncthreads();
        #pragma unroll
        for (int ks = 0; ks < 32; ks += 16) {
            wmma::fragment<wmma::matrix_a, 16, 16, 16, __half, ALay> af[4];
            wmma::fragment<wmma::matrix_b, 16, 16, 16, __half, BLay> bf[2];
            #pragma unroll
            for (int i = 0; i < 4; i++) {
                if constexpr (AT == 0)
                    wmma::load_matrix_sync(af[i], As + (warp_m + i * 16) * PAD32 + ks, PAD32);
                else
                    wmma::load_matrix_sync(af[i], As + ks * PADM + warp_m + i * 16, PADM);
            }
            #pragma unroll
            for (int j = 0; j < 2; j++) {
                if constexpr (BT == 0)
                    wmma::load_matrix_sync(bf[j], Bs + ks * PADM + warp_n + j * 16, PADM);
                else
                    wmma::load_matrix_sync(bf[j], Bs + (warp_n + j * 16) * PAD32 + ks, PAD32);
            }
            #pragma unroll
            for (int i = 0; i < 4; i++)
                #pragma unroll
                for (int j = 0; j < 2; j++)
                    wmma::mma_sync(acc[i][j], af[i], bf[j], acc[i][j]);
        }
        __syncthreads();
    }

    if constexpr (OUTH == 0) {
        float* Cb = (float*)Cv;
        #pragma unroll
        for (int i = 0; i < 4; i++)
            #pragma unroll
            for (int j = 0; j < 2; j++) {
                #pragma unroll
                for (int t = 0; t < acc[i][j].num_elements; t++)
                    acc[i][j].x[t] *= alpha;
                wmma::store_matrix_sync(Cb + (long)(warp_m + i * 16) * ldc + warp_n + j * 16,
                                        acc[i][j], ldc, wmma::mem_row_major);
            }
    } else {
        __half* Cb = (__half*)Cv;
        float* patch = ((float*)As) + wid * 256;   // 1KB/warp inside As (8KB total)
        const int lane = tid & 31;
        #pragma unroll
        for (int i = 0; i < 4; i++)
            #pragma unroll
            for (int j = 0; j < 2; j++) {
                wmma::store_matrix_sync(patch, acc[i][j], 16, wmma::mem_row_major);
                __syncwarp();
                #pragma unroll
                for (int e = 0; e < 8; e++) {
                    int el = lane + e * 32;
                    int rr = el >> 4, cc = el & 15;
                    Cb[(long)(warp_m + i * 16 + rr) * ldc + warp_n + j * 16 + cc] =
                        __float2half(patch[el] * alpha);
                }
                __syncwarp();
            }
    }
}

// ---------------- generic fp16 kernel wrapper ----------------
// blockIdx.x = m_block*2 + n_block; blockIdx.y = k-split chunk; blockIdx.z = batch.
template <int AT, int BT, int OUTH>
__global__ __launch_bounds__(256, 2) void gemm_k(
    const __half* __restrict__ A, const __half* __restrict__ B, void* Cv,
    int lda, int ldb, int ldc, int Kc,
    long sAz, long sBz, long sCz, long sCy, float alpha)
{
    __shared__ __align__(32) __half As[128 * PAD32];
    __shared__ __align__(32) __half Bs[128 * PAD32];
    const int bx = blockIdx.x, by = blockIdx.y, bz = blockIdx.z;
    const int m0 = (bx >> 1) * 128, n0 = (bx & 1) * 128;

    const __half* Ab;
    if constexpr (AT == 0) Ab = A + (long)bz * sAz + (long)m0 * lda + (long)by * Kc;
    else                   Ab = A + (long)bz * sAz + (long)by * Kc * lda + m0;
    const __half* Bb;
    if constexpr (BT == 0) Bb = B + (long)bz * sBz + (long)by * Kc * ldb + n0;
    else                   Bb = B + (long)bz * sBz + (long)n0 * ldb + (long)by * Kc;
    const long coff = (long)bz * sCz + (long)by * sCy + (long)m0 * ldc + n0;
    void* Cb;
    if constexpr (OUTH == 0) Cb = (void*)((float*)Cv + coff);
    else                     Cb = (void*)((__half*)Cv + coff);

    gemm_body<AT, BT, OUTH>(Ab, Bb, Cb, lda, ldb, ldc, Kc, alpha, As, Bs);
}

// ---------------- persistent mid kernel: reduce + R2/P2 -> U2 -> T2 ----------
// grid = 64 CTAs (all resident), 3 stages with software grid barriers.
#define NMID 64
__global__ __launch_bounds__(256, 2) void mid_chain(
    const float* __restrict__ Wo, const float* __restrict__ Wv,
    const float* __restrict__ Wk, const float* __restrict__ Wq,
    const float* __restrict__ part,
    __half* __restrict__ Gh, __half* __restrict__ R2, __half* __restrict__ P2,
    __half* __restrict__ U2, __half* __restrict__ T2)
{
    __shared__ __align__(32) __half As[128 * PAD32];
    __shared__ __align__(32) __half Bs[128 * PAD32];
    const int cta = blockIdx.x;
    const long EE = (long)E_ * E_;

    // ---- stage 0: CTAs 0-7 weight products; CTAs 8-63 split-K reduce ----
    if (cta < 8) {
        const int bx = cta & 3;
        const int m0 = (bx >> 1) * 128, n0 = (bx & 1) * 128;
        if (cta < 4)
            gemm_body<0, 0, 1>(Wo + (long)m0 * E_, Wv + n0,
                               (void*)(R2 + (long)m0 * E_ + n0),
                               E_, E_, E_, E_, 1.0f, As, Bs);
        else
            gemm_body<1, 0, 1>(Wk + m0, Wq + n0,
                               (void*)(P2 + (long)m0 * E_ + n0),
                               E_, E_, E_, E_, 1.0f, As, Bs);
    } else {
        for (int i4 = (cta - 8) * 256 + threadIdx.x; i4 < B_ * E_ * E_ / 4;
             i4 += (NMID - 8) * 256) {
            const int b = i4 >> 14;                  // E_*E_/4 = 16384 per batch
            const int r = i4 & 16383;
            const float4* p = (const float4*)part + (long)b * GSPLIT * 16384 + r;
            float4 s = make_float4(0.f, 0.f, 0.f, 0.f);
            #pragma unroll
            for (int q = 0; q < GSPLIT; q++) {
                float4 v = p[(long)q * 16384];
                s.x += v.x; s.y += v.y; s.z += v.z; s.w += v.w;
            }
            __half2 h0 = __floats2half2_rn(s.x, s.y);
            __half2 h1 = __floats2half2_rn(s.z, s.w);
            uint2 o;
            o.x = *(uint32_t*)&h0;
            o.y = *(uint32_t*)&h1;
            *((uint2*)Gh + i4) = o;
        }
    }
    grid_barrier(NMID);

    // ---- stage 1: CTAs 0-15: U2_b = R2 · G_b ----
    if (cta < 16) {
        const int bz = cta >> 2, bx = cta & 3;
        const int m0 = (bx >> 1) * 128, n0 = (bx & 1) * 128;
        gemm_body<0, 0, 1>(R2 + (long)m0 * E_, Gh + (long)bz * EE + n0,
                           (void*)(U2 + (long)bz * EE + (long)m0 * E_ + n0),
                           E_, E_, E_, E_, 1.0f, As, Bs);
    }
    grid_barrier(NMID);

    // ---- stage 2: CTAs 0-15: T2_b = U2_b · P2 ----
    if (cta < 16) {
        const int bz = cta >> 2, bx = cta & 3;
        const int m0 = (bx >> 1) * 128, n0 = (bx & 1) * 128;
        gemm_body<0, 0, 1>(U2 + (long)bz * EE + (long)m0 * E_, P2 + n0,
                           (void*)(T2 + (long)bz * EE + (long)m0 * E_ + n0),
                           E_, E_, E_, E_, 1.0f, As, Bs);
    }
}

// ---------------- convert x -> fp16 transposed [b][e][s] ----------
__global__ __launch_bounds__(256) void convert_x(
    const float* __restrict__ x, __half* __restrict__ xTh)
{
    __shared__ __half sh[32][33];
    const int e0 = blockIdx.x * 32, s0 = blockIdx.y * 32, b = blockIdx.z;
    const int j = threadIdx.x & 31, i0 = (threadIdx.x >> 5) * 4;
    const long xb = (long)b * S_ * E_;
    #pragma unroll
    for (int ii = 0; ii < 4; ii++) {
        int i = i0 + ii;
        sh[i][j] = __float2half(x[xb + (long)(s0 + i) * E_ + e0 + j]);
    }
    __syncthreads();
    const long xtb = (long)b * E_ * S_;
    #pragma unroll
    for (int ii = 0; ii < 4; ii++) {
        int i = i0 + ii;
        xTh[xtb + (long)(e0 + i) * S_ + s0 + j] = sh[j][i];
    }
}

// ---------------- launch ----------------
extern "C" void kernel_launch(void* const* d_in, const int* in_sizes, int n_in,
                              void* d_out, int out_size)
{
    const float* x  = (const float*)d_in[0];
    const float* Wq = (const float*)d_in[1];
    const float* Wk = (const float*)d_in[2];
    const float* Wv = (const float*)d_in[3];
    const float* Wo = (const float*)d_in[4];
    float* out = (float*)d_out;

    __half *pxTh, *pGh, *pR2h, *pP2h, *pU2h, *pT2h;
    float *pPart;
    cudaGetSymbolAddress((void**)&pxTh, g_xTh);
    cudaGetSymbolAddress((void**)&pPart, g_part);
    cudaGetSymbolAddress((void**)&pGh, g_Gh);
    cudaGetSymbolAddress((void**)&pR2h, g_R2h);
    cudaGetSymbolAddress((void**)&pP2h, g_P2h);
    cudaGetSymbolAddress((void**)&pU2h, g_U2h);
    cudaGetSymbolAddress((void**)&pT2h, g_T2h);

    const long EE = (long)E_ * E_;
    const long ES = (long)E_ * S_;

    // 1) convert x -> fp16 transposed
    convert_x<<<dim3(E_ / 32, S_ / 32, B_), 256>>>(x, pxTh);

    // 2) Gram partials: part[b][p][e][f] = sum over S-chunk of xT[e,s] xT[f,s]
    gemm_k<0, 1, 0><<<dim3(4, GSPLIT, B_), 256>>>(
        pxTh, pxTh, pPart, S_, S_, E_, S_ / GSPLIT,
        ES, ES, (long)GSPLIT * EE, EE, 1.0f);

    // 3) persistent middle: reduce + R2/P2 (concurrent) -> U2 -> T2
    mid_chain<<<NMID, 256>>>(Wo, Wv, Wk, Wq, pPart, pGh, pR2h, pP2h, pU2h, pT2h);

    // 4) final: out[s,g] = 1e-11 * sum_f xT[f,s] * T2[g,f]  (AT=1, BT=1)
    gemm_k<1, 1, 0><<<dim3((S_ / 128) * 2, 1, B_), 256>>>(
        pxTh, pT2h, out, S_, E_, E_, E_,
        ES, EE, (long)S_ * E_, 0, 1e-11f);
}

// round 12
// speedup vs baseline: 1.9384x; 1.1363x over previous
#include <cuda_runtime.h>
#include <cuda_fp16.h>
#include <mma.h>
#include <cstdint>
#include <type_traits>

using namespace nvcuda;

// FHEAttention B=4,S=4096,E=256 — linearized: out = 1e-11 * x @ P @ (x^T x) @ R
// All GEMMs on HMMA (wmma fp16, fp32 accumulate). 1e-11 applied in final epilogue.
// Heavy GEMM bodies use double-buffered cp.async pipelining.
// Middle section (reduce + R2/P2 + U2 + T2) is ONE persistent 64-CTA kernel
// with software grid barriers.

#define B_ 4
#define S_ 4096
#define E_ 256
#define GSPLIT 8
#define PAD32 40
#define PADM 136
#define ABUF 5120          // halves per smem buffer (fits 128*PAD32 and 32*PADM)

// ---------------- scratch ----------------
__device__ __align__(128) __half g_xTh[B_ * E_ * S_];    // x^T fp16
__device__ __align__(128) float  g_part[B_ * GSPLIT * E_ * E_];
__device__ __align__(128) __half g_Gh[B_ * E_ * E_];
__device__ __align__(128) __half g_R2h[E_ * E_];
__device__ __align__(128) __half g_P2h[E_ * E_];
__device__ __align__(128) __half g_U2h[B_ * E_ * E_];
__device__ __align__(128) __half g_T2h[B_ * E_ * E_];
__device__ unsigned g_bar_arr = 0;
__device__ unsigned g_bar_gen = 0;

// ---------------- cp.async helpers ----------------
__device__ __forceinline__ void cp16(void* smem_dst, const void* gsrc) {
    uint32_t s = (uint32_t)__cvta_generic_to_shared(smem_dst);
    asm volatile("cp.async.cg.shared.global [%0], [%1], 16;" :: "r"(s), "l"(gsrc));
}
#define CP_COMMIT() asm volatile("cp.async.commit_group;")
#define CP_WAIT1()  asm volatile("cp.async.wait_group 1;")
#define CP_WAIT0()  asm volatile("cp.async.wait_group 0;")

// ---------------- software grid barrier (all CTAs resident) ----------------
__device__ __forceinline__ void grid_barrier(unsigned nCTA) {
    __syncthreads();
    if (threadIdx.x == 0) {
        unsigned gen = atomicAdd(&g_bar_gen, 0u);
        __threadfence();
        unsigned t = atomicAdd(&g_bar_arr, 1u);
        if (t == nCTA - 1) {
            atomicExch(&g_bar_arr, 0u);
            __threadfence();
            atomicAdd(&g_bar_gen, 1u);
        } else {
            while (atomicAdd(&g_bar_gen, 0u) == gen) { }
        }
    }
    __syncthreads();
}

// ---------------- shared epilogue ----------------
template <int OUTH>
__device__ __forceinline__ void gemm_epilogue(
    wmma::fragment<wmma::accumulator, 16, 16, 16, float> (&acc)[4][2],
    void* Cv, int ldc, float alpha, __half* As, int warp_m, int warp_n)
{
    const int tid = threadIdx.x, wid = tid >> 5;
    if constexpr (OUTH == 0) {
        float* Cb = (float*)Cv;
        #pragma unroll
        for (int i = 0; i < 4; i++)
            #pragma unroll
            for (int j = 0; j < 2; j++) {
                #pragma unroll
                for (int t = 0; t < acc[i][j].num_elements; t++)
                    acc[i][j].x[t] *= alpha;
                wmma::store_matrix_sync(Cb + (long)(warp_m + i * 16) * ldc + warp_n + j * 16,
                                        acc[i][j], ldc, wmma::mem_row_major);
            }
    } else {
        __half* Cb = (__half*)Cv;
        float* patch = ((float*)As) + wid * 256;   // 1KB/warp (8KB total, fits ABUF*2)
        const int lane = tid & 31;
        #pragma unroll
        for (int i = 0; i < 4; i++)
            #pragma unroll
            for (int j = 0; j < 2; j++) {
                wmma::store_matrix_sync(patch, acc[i][j], 16, wmma::mem_row_major);
                __syncwarp();
                #pragma unroll
                for (int e = 0; e < 8; e++) {
                    int el = lane + e * 32;
                    int rr = el >> 4, cc = el & 15;
                    Cb[(long)(warp_m + i * 16 + rr) * ldc + warp_n + j * 16 + cc] =
                        __float2half(patch[el] * alpha);
                }
                __syncwarp();
            }
    }
}

// ---------------- pipelined fp16 GEMM body (cp.async double-buffered) --------
// C[m,n] = alpha * sum_k A(m,k)*B(k,n); 128x128 tile; pointers pre-offset.
// AT=0: A [m][k]; AT=1: A [k][m]. BT=0: B [k][n]; BT=1: B [n][k].
template <int AT, int BT, int OUTH>
__device__ __forceinline__ void gemm_body_pipe(
    const __half* Ap, const __half* Bp, void* Cv,
    int lda, int ldb, int ldc, int Kc, float alpha,
    __half* As, __half* Bs)
{
    const int tid = threadIdx.x, wid = tid >> 5;
    const int warp_m = (wid & 1) * 64;
    const int warp_n = (wid >> 1) * 32;

    wmma::fragment<wmma::accumulator, 16, 16, 16, float> acc[4][2];
    #pragma unroll
    for (int i = 0; i < 4; i++)
        #pragma unroll
        for (int j = 0; j < 2; j++)
            wmma::fill_fragment(acc[i][j], 0.0f);

    using ALay = std::conditional_t<AT == 0, wmma::row_major, wmma::col_major>;
    using BLay = std::conditional_t<BT == 0, wmma::row_major, wmma::col_major>;

    auto stage = [&](int kt, int buf) {
        #pragma unroll
        for (int q = 0; q < 2; q++) {
            int idx = tid + q * 256;
            if constexpr (AT == 0) {
                int r = idx >> 2, c = (idx & 3) * 8;
                cp16(As + buf * ABUF + r * PAD32 + c, Ap + (long)r * lda + kt + c);
            } else {
                int r = idx >> 4, c = (idx & 15) * 8;
                cp16(As + buf * ABUF + r * PADM + c, Ap + (long)(kt + r) * lda + c);
            }
        }
        #pragma unroll
        for (int q = 0; q < 2; q++) {
            int idx = tid + q * 256;
            if constexpr (BT == 0) {
                int r = idx >> 4, c = (idx & 15) * 8;
                cp16(Bs + buf * ABUF + r * PADM + c, Bp + (long)(kt + r) * ldb + c);
            } else {
                int r = idx >> 2, c = (idx & 3) * 8;
                cp16(Bs + buf * ABUF + r * PAD32 + c, Bp + (long)r * ldb + kt + c);
            }
        }
    };

    const int nIter = Kc >> 5;
    int buf = 0;
    stage(0, 0);
    CP_COMMIT();
    for (int it = 0; it < nIter; it++) {
        if (it + 1 < nIter) {
            stage((it + 1) * 32, buf ^ 1);
            CP_COMMIT();
            CP_WAIT1();
        } else {
            CP_WAIT0();
        }
        __syncthreads();
        const __half* Ab = As + buf * ABUF;
        const __half* Bb = Bs + buf * ABUF;
        #pragma unroll
        for (int ks = 0; ks < 32; ks += 16) {
            wmma::fragment<wmma::matrix_a, 16, 16, 16, __half, ALay> af[4];
            wmma::fragment<wmma::matrix_b, 16, 16, 16, __half, BLay> bf[2];
            #pragma unroll
            for (int i = 0; i < 4; i++) {
                if constexpr (AT == 0)
                    wmma::load_matrix_sync(af[i], Ab + (warp_m + i * 16) * PAD32 + ks, PAD32);
                else
                    wmma::load_matrix_sync(af[i], Ab + ks * PADM + warp_m + i * 16, PADM);
            }
            #pragma unroll
            for (int j = 0; j < 2; j++) {
                if constexpr (BT == 0)
                    wmma::load_matrix_sync(bf[j], Bb + ks * PADM + warp_n + j * 16, PADM);
                else
                    wmma::load_matrix_sync(bf[j], Bb + (warp_n + j * 16) * PAD32 + ks, PAD32);
            }
            #pragma unroll
            for (int i = 0; i < 4; i++)
                #pragma unroll
                for (int j = 0; j < 2; j++)
                    wmma::mma_sync(acc[i][j], af[i], bf[j], acc[i][j]);
        }
        buf ^= 1;
        __syncthreads();
    }
    gemm_epilogue<OUTH>(acc, Cv, ldc, alpha, As, warp_m, warp_n);
}

// ---------------- generic body for fp32-staged operands (weights) -----------
template <int AT, int OUTH>
__device__ __forceinline__ void gemm_body_f32(
    const float* Ap, const float* Bp, void* Cv,
    int lda, int ldb, int ldc, int Kc, float alpha,
    __half* As, __half* Bs)
{
    const int tid = threadIdx.x, wid = tid >> 5;
    const int warp_m = (wid & 1) * 64;
    const int warp_n = (wid >> 1) * 32;

    wmma::fragment<wmma::accumulator, 16, 16, 16, float> acc[4][2];
    #pragma unroll
    for (int i = 0; i < 4; i++)
        #pragma unroll
        for (int j = 0; j < 2; j++)
            wmma::fill_fragment(acc[i][j], 0.0f);

    using ALay = std::conditional_t<AT == 0, wmma::row_major, wmma::col_major>;

    for (int kt = 0; kt < Kc; kt += 32) {
        if constexpr (AT == 0) {
            const float* Aq = Ap + kt;
            #pragma unroll
            for (int q = 0; q < 4; q++) {
                int idx = tid + q * 256;
                int r = idx >> 3, c = (idx & 7) * 4;
                float4 v = *(const float4*)(Aq + (long)r * lda + c);
                __half2 h0 = __floats2half2_rn(v.x, v.y);
                __half2 h1 = __floats2half2_rn(v.z, v.w);
                uint2 o; o.x = *(uint32_t*)&h0; o.y = *(uint32_t*)&h1;
                *(uint2*)(As + r * PAD32 + c) = o;
            }
        } else {
            const float* Aq = Ap + (long)kt * lda;
            #pragma unroll
            for (int q = 0; q < 4; q++) {
                int idx = tid + q * 256;
                int r = idx >> 5, c = (idx & 31) * 4;
                float4 v = *(const float4*)(Aq + (long)r * lda + c);
                __half2 h0 = __floats2half2_rn(v.x, v.y);
                __half2 h1 = __floats2half2_rn(v.z, v.w);
                uint2 o; o.x = *(uint32_t*)&h0; o.y = *(uint32_t*)&h1;
                *(uint2*)(As + r * PADM + c) = o;
            }
        }
        {
            const float* Bq = Bp + (long)kt * ldb;
            #pragma unroll
            for (int q = 0; q < 4; q++) {
                int idx = tid + q * 256;
                int r = idx >> 5, c = (idx & 31) * 4;
                float4 v = *(const float4*)(Bq + (long)r * ldb + c);
                __half2 h0 = __floats2half2_rn(v.x, v.y);
                __half2 h1 = __floats2half2_rn(v.z, v.w);
                uint2 o; o.x = *(uint32_t*)&h0; o.y = *(uint32_t*)&h1;
                *(uint2*)(Bs + r * PADM + c) = o;
            }
        }
        __syncthreads();
        #pragma unroll
        for (int ks = 0; ks < 32; ks += 16) {
            wmma::fragment<wmma::matrix_a, 16, 16, 16, __half, ALay> af[4];
            wmma::fragment<wmma::matrix_b, 16, 16, 16, __half, wmma::row_major> bf[2];
            #pragma unroll
            for (int i = 0; i < 4; i++) {
                if constexpr (AT == 0)
                    wmma::load_matrix_sync(af[i], As + (warp_m + i * 16) * PAD32 + ks, PAD32);
                else
                    wmma::load_matrix_sync(af[i], As + ks * PADM + warp_m + i * 16, PADM);
            }
            #pragma unroll
            for (int j = 0; j < 2; j++)
                wmma::load_matrix_sync(bf[j], Bs + ks * PADM + warp_n + j * 16, PADM);
            #pragma unroll
            for (int i = 0; i < 4; i++)
                #pragma unroll
                for (int j = 0; j < 2; j++)
                    wmma::mma_sync(acc[i][j], af[i], bf[j], acc[i][j]);
        }
        __syncthreads();
    }
    gemm_epilogue<OUTH>(acc, Cv, ldc, alpha, As, warp_m, warp_n);
}

// ---------------- pipelined kernel wrapper ----------------
// blockIdx.x = m_block*2 + n_block; blockIdx.y = k-split chunk; blockIdx.z = batch.
template <int AT, int BT, int OUTH>
__global__ __launch_bounds__(256, 2) void gemm_k(
    const __half* __restrict__ A, const __half* __restrict__ B, void* Cv,
    int lda, int ldb, int ldc, int Kc,
    long sAz, long sBz, long sCz, long sCy, float alpha)
{
    __shared__ __align__(32) __half As[2 * ABUF];
    __shared__ __align__(32) __half Bs[2 * ABUF];
    const int bx = blockIdx.x, by = blockIdx.y, bz = blockIdx.z;
    const int m0 = (bx >> 1) * 128, n0 = (bx & 1) * 128;

    const __half* Ab;
    if constexpr (AT == 0) Ab = A + (long)bz * sAz + (long)m0 * lda + (long)by * Kc;
    else                   Ab = A + (long)bz * sAz + (long)by * Kc * lda + m0;
    const __half* Bb;
    if constexpr (BT == 0) Bb = B + (long)bz * sBz + (long)by * Kc * ldb + n0;
    else                   Bb = B + (long)bz * sBz + (long)n0 * ldb + (long)by * Kc;
    const long coff = (long)bz * sCz + (long)by * sCy + (long)m0 * ldc + n0;
    void* Cb;
    if constexpr (OUTH == 0) Cb = (void*)((float*)Cv + coff);
    else                     Cb = (void*)((__half*)Cv + coff);

    gemm_body_pipe<AT, BT, OUTH>(Ab, Bb, Cb, lda, ldb, ldc, Kc, alpha, As, Bs);
}

// ---------------- persistent mid kernel: reduce + R2/P2 -> U2 -> T2 ----------
#define NMID 64
__global__ __launch_bounds__(256, 2) void mid_chain(
    const float* __restrict__ Wo, const float* __restrict__ Wv,
    const float* __restrict__ Wk, const float* __restrict__ Wq,
    const float* __restrict__ part,
    __half* __restrict__ Gh, __half* __restrict__ R2, __half* __restrict__ P2,
    __half* __restrict__ U2, __half* __restrict__ T2)
{
    __shared__ __align__(32) __half As[2 * ABUF];
    __shared__ __align__(32) __half Bs[2 * ABUF];
    const int cta = blockIdx.x;
    const long EE = (long)E_ * E_;

    // ---- stage 0: CTAs 0-7 weight products; CTAs 8-63 split-K reduce ----
    if (cta < 8) {
        const int bx = cta & 3;
        const int m0 = (bx >> 1) * 128, n0 = (bx & 1) * 128;
        if (cta < 4)
            gemm_body_f32<0, 1>(Wo + (long)m0 * E_, Wv + n0,
                                (void*)(R2 + (long)m0 * E_ + n0),
                                E_, E_, E_, E_, 1.0f, As, Bs);
        else
            gemm_body_f32<1, 1>(Wk + m0, Wq + n0,
                                (void*)(P2 + (long)m0 * E_ + n0),
                                E_, E_, E_, E_, 1.0f, As, Bs);
    } else {
        for (int i4 = (cta - 8) * 256 + threadIdx.x; i4 < B_ * E_ * E_ / 4;
             i4 += (NMID - 8) * 256) {
            const int b = i4 >> 14;
            const int r = i4 & 16383;
            const float4* p = (const float4*)part + (long)b * GSPLIT * 16384 + r;
            float4 s = make_float4(0.f, 0.f, 0.f, 0.f);
            #pragma unroll
            for (int q = 0; q < GSPLIT; q++) {
                float4 v = p[(long)q * 16384];
                s.x += v.x; s.y += v.y; s.z += v.z; s.w += v.w;
            }
            __half2 h0 = __floats2half2_rn(s.x, s.y);
            __half2 h1 = __floats2half2_rn(s.z, s.w);
            uint2 o;
            o.x = *(uint32_t*)&h0;
            o.y = *(uint32_t*)&h1;
            *((uint2*)Gh + i4) = o;
        }
    }
    grid_barrier(NMID);

    // ---- stage 1: CTAs 0-15: U2_b = R2 · G_b ----
    if (cta < 16) {
        const int bz = cta >> 2, bx = cta & 3;
        const int m0 = (bx >> 1) * 128, n0 = (bx & 1) * 128;
        gemm_body_pipe<0, 0, 1>(R2 + (long)m0 * E_, Gh + (long)bz * EE + n0,
                                (void*)(U2 + (long)bz * EE + (long)m0 * E_ + n0),
                                E_, E_, E_, E_, 1.0f, As, Bs);
    }
    grid_barrier(NMID);

    // ---- stage 2: CTAs 0-15: T2_b = U2_b · P2 ----
    if (cta < 16) {
        const int bz = cta >> 2, bx = cta & 3;
        const int m0 = (bx >> 1) * 128, n0 = (bx & 1) * 128;
        gemm_body_pipe<0, 0, 1>(U2 + (long)bz * EE + (long)m0 * E_, P2 + n0,
                                (void*)(T2 + (long)bz * EE + (long)m0 * E_ + n0),
                                E_, E_, E_, E_, 1.0f, As, Bs);
    }
}

// ---------------- convert x -> fp16 transposed [b][e][s] ----------
__global__ __launch_bounds__(256) void convert_x(
    const float* __restrict__ x, __half* __restrict__ xTh)
{
    __shared__ __half sh[32][33];
    const int e0 = blockIdx.x * 32, s0 = blockIdx.y * 32, b = blockIdx.z;
    const int j = threadIdx.x & 31, i0 = (threadIdx.x >> 5) * 4;
    const long xb = (long)b * S_ * E_;
    #pragma unroll
    for (int ii = 0; ii < 4; ii++) {
        int i = i0 + ii;
        sh[i][j] = __float2half(x[xb + (long)(s0 + i) * E_ + e0 + j]);
    }
    __syncthreads();
    const long xtb = (long)b * E_ * S_;
    #pragma unroll
    for (int ii = 0; ii < 4; ii++) {
        int i = i0 + ii;
        xTh[xtb + (long)(e0 + i) * S_ + s0 + j] = sh[j][i];
    }
}

// ---------------- launch ----------------
extern "C" void kernel_launch(void* const* d_in, const int* in_sizes, int n_in,
                              void* d_out, int out_size)
{
    const float* x  = (const float*)d_in[0];
    const float* Wq = (const float*)d_in[1];
    const float* Wk = (const float*)d_in[2];
    const float* Wv = (const float*)d_in[3];
    const float* Wo = (const float*)d_in[4];
    float* out = (float*)d_out;

    __half *pxTh, *pGh, *pR2h, *pP2h, *pU2h, *pT2h;
    float *pPart;
    cudaGetSymbolAddress((void**)&pxTh, g_xTh);
    cudaGetSymbolAddress((void**)&pPart, g_part);
    cudaGetSymbolAddress((void**)&pGh, g_Gh);
    cudaGetSymbolAddress((void**)&pR2h, g_R2h);
    cudaGetSymbolAddress((void**)&pP2h, g_P2h);
    cudaGetSymbolAddress((void**)&pU2h, g_U2h);
    cudaGetSymbolAddress((void**)&pT2h, g_T2h);

    const long EE = (long)E_ * E_;
    const long ES = (long)E_ * S_;

    // 1) convert x -> fp16 transposed
    convert_x<<<dim3(E_ / 32, S_ / 32, B_), 256>>>(x, pxTh);

    // 2) Gram partials: part[b][p][e][f] = sum over S-chunk of xT[e,s] xT[f,s]
    gemm_k<0, 1, 0><<<dim3(4, GSPLIT, B_), 256>>>(
        pxTh, pxTh, pPart, S_, S_, E_, S_ / GSPLIT,
        ES, ES, (long)GSPLIT * EE, EE, 1.0f);

    // 3) persistent middle: reduce + R2/P2 (concurrent) -> U2 -> T2
    mid_chain<<<NMID, 256>>>(Wo, Wv, Wk, Wq, pPart, pGh, pR2h, pP2h, pU2h, pT2h);

    // 4) final: out[s,g] = 1e-11 * sum_f xT[f,s] * T2[g,f]  (AT=1, BT=1)
    gemm_k<1, 1, 0><<<dim3((S_ / 128) * 2, 1, B_), 256>>>(
        pxTh, pT2h, out, S_, E_, E_, E_,
        ES, EE, (long)S_ * E_, 0, 1e-11f);
}